// round 6
// baseline (speedup 1.0000x reference)
#include <cuda_runtime.h>

// Problem constants
#define BB 128
#define DD 128
#define TT 2048
#define CC 64
#define TILE_T 512
#define NTILES 4
#define DCH 32
#define NCH 4
#define THREADS 512
#define NWARP (THREADS / 32)     // 16
#define PITCH 33
#define GRID (BB * NTILES)       // 512
#define NREP 8                   // g_S replicas to spread L2 atomic conflicts
#define ZOFF (TILE_T * PITCH)    // zero-region base index inside tile (16896)
#define PRE_N (TILE_T + CC * 3)  // padded order capacity (704)

// Scratch (allocation-free; self-reset each run so graph replays are identical)
__device__ float        g_S[NREP][CC * DD];
__device__ float        g_loss;
__device__ int          g_count[CC];
__device__ unsigned int g_done;

// Dynamic smem layout (bytes), 16B-aligned fields
#define SM_TILE_OFF   0
#define SM_TILE_BYTES ((TILE_T * PITCH + 32) * 4)          // 67712 (incl. zero region)
#define SM_PRE_OFF    (SM_TILE_OFF + SM_TILE_BYTES)
#define SM_PRE_BYTES  (PRE_N * 4)                          // 2816
#define SM_LABS_OFF   (SM_PRE_OFF + SM_PRE_BYTES)
#define SM_HIST_OFF   (SM_LABS_OFF + TILE_T)
#define SM_HS_OFF     (SM_HIST_OFF + CC * 4)
#define SM_CUR_OFF    (SM_HS_OFF + CC * 4)
#define SM_TICK4_OFF  (SM_CUR_OFF + CC * 4)
#define SM_WRED_OFF   (SM_TICK4_OFF + NCH * 4)
#define SM_WTOT_OFF   (SM_WRED_OFF + NWARP * 4)
#define SM_TICK_OFF   (SM_WTOT_OFF + 8)
#define SM_TOTAL      (SM_TICK_OFF + 16)

__global__ __launch_bounds__(THREADS, 3)
void cl_fused_kernel(const float* __restrict__ feature,
                     const int* __restrict__ label,
                     const float* __restrict__ centers,
                     float* __restrict__ out) {
    extern __shared__ char sm[];
    float*         tile    = (float*)(sm + SM_TILE_OFF);
    unsigned int*  pre     = (unsigned int*)(sm + SM_PRE_OFF);
    unsigned char* labs    = (unsigned char*)(sm + SM_LABS_OFF);
    int*           hist    = (int*)(sm + SM_HIST_OFF);
    unsigned int*  hs      = (unsigned int*)(sm + SM_HS_OFF); // starts | (m<<16)
    int*           cursor  = (int*)(sm + SM_CUR_OFF);
    int*           tickets = (int*)(sm + SM_TICK4_OFF);
    float*         wred    = (float*)(sm + SM_WRED_OFF);
    int*           wtot    = (int*)(sm + SM_WTOT_OFF);
    unsigned int*  tick    = (unsigned int*)(sm + SM_TICK_OFF);

    const int tid  = threadIdx.x;
    const int lane = tid & 31;
    const int wid  = tid >> 5;
    const int b    = blockIdx.x >> 2;
    const int t0   = (blockIdx.x & 3) * TILE_T;
    const int rep  = blockIdx.x & (NREP - 1);

    const int t4   = tid & 127;       // float4 slot along t
    const int dd0  = tid >> 7;        // 0..3
    const int sw   = t4 & 31;         // swizzle key
    const int trow = t4 * (4 * PITCH);

    const float4* f4b = (const float4*)feature
        + ((long long)b * DD) * (TT / 4) + (t0 >> 2) + t4;

    float4 v[4];
    // Prefetch chunk 0 / wave 0 FIRST — latency hides behind the prologue.
    #pragma unroll
    for (int k = 0; k < 4; k++)
        v[k] = f4b[(long long)(dd0 + 4 * k) * (TT / 4)];

    // ---- Prologue: histogram, padded scan, packed-order scatter ----
    if (tid < CC) { hist[tid] = 0; }
    if (tid < NCH) tickets[tid] = 0;
    if (tid < 32) tile[ZOFF + tid] = 0.0f;            // zero region for padding
    for (int i = tid; i < PRE_N; i += THREADS)
        pre[i] = (unsigned int)ZOFF;                  // sentinel -> reads zeros
    __syncthreads();

    if (tid < TILE_T) {
        int l = label[b * TT + t0 + tid] & (CC - 1);
        labs[tid] = (unsigned char)l;
        atomicAdd(&hist[l], 1);
    }
    __syncthreads();

    {   // exclusive scan of 4-padded sizes (warps 0/1 + carry)
        int m  = (tid < CC) ? hist[tid] : 0;
        int p4 = (m + 3) & ~3;
        int incl = p4;
        #pragma unroll
        for (int o = 1; o < 32; o <<= 1) {
            int n = __shfl_up_sync(0xffffffffu, incl, o);
            if (lane >= o) incl += n;
        }
        if (wid < 2 && lane == 31) wtot[wid] = incl;
        __syncthreads();
        if (tid < CC) {
            int st = incl - p4 + (wid == 1 ? wtot[0] : 0);
            hs[tid]     = (unsigned int)st | ((unsigned int)m << 16);
            cursor[tid] = st;
        }
        __syncthreads();
    }

    if (tid < TILE_T) {
        int pos = atomicAdd(&cursor[labs[tid]], 1);
        // packed row descriptor: base = t*PITCH (15 bits), key = (t>>2)&31
        pre[pos] = (unsigned int)(tid * PITCH) | (((unsigned int)(tid >> 2) & 31u) << 16);
    }
    if (tid < CC) atomicAdd(&g_count[tid], hist[tid]);

    float sumsq = 0.0f;

    // ---- Main loop over 4 d-chunks ----
    for (int ch = 0; ch < NCH; ch++) {
        __syncthreads();   // tile free (previous gather done)

        // store wave 0 (v holds it), accumulate sum of squares
        #pragma unroll
        for (int k = 0; k < 4; k++) {
            int base = trow + ((dd0 + 4 * k) ^ sw);
            tile[base]             = v[k].x;
            tile[base + PITCH]     = v[k].y;
            tile[base + 2 * PITCH] = v[k].z;
            tile[base + 3 * PITCH] = v[k].w;
            sumsq = fmaf(v[k].x, v[k].x, sumsq);
            sumsq = fmaf(v[k].y, v[k].y, sumsq);
            sumsq = fmaf(v[k].z, v[k].z, sumsq);
            sumsq = fmaf(v[k].w, v[k].w, sumsq);
        }
        // load + store wave 1
        {
            const float4* f4c = f4b + (long long)(ch * DCH) * (TT / 4);
            float4 w[4];
            #pragma unroll
            for (int k = 0; k < 4; k++)
                w[k] = f4c[(long long)(dd0 + 4 * k + 16) * (TT / 4)];
            #pragma unroll
            for (int k = 0; k < 4; k++) {
                int base = trow + ((dd0 + 4 * k + 16) ^ sw);
                tile[base]             = w[k].x;
                tile[base + PITCH]     = w[k].y;
                tile[base + 2 * PITCH] = w[k].z;
                tile[base + 3 * PITCH] = w[k].w;
                sumsq = fmaf(w[k].x, w[k].x, sumsq);
                sumsq = fmaf(w[k].y, w[k].y, sumsq);
                sumsq = fmaf(w[k].z, w[k].z, sumsq);
                sumsq = fmaf(w[k].w, w[k].w, sumsq);
            }
        }
        __syncthreads();   // tile ready

        // prefetch next chunk wave 0; DRAM latency hides behind the gather
        if (ch < NCH - 1) {
            const float4* f4n = f4b + (long long)((ch + 1) * DCH) * (TT / 4);
            #pragma unroll
            for (int k = 0; k < 4; k++)
                v[k] = f4n[(long long)(dd0 + 4 * k) * (TT / 4)];
        }

        // Work-stealing gather: warps grab classes off a ticket counter.
        float* gS = &g_S[rep][ch * DCH + lane];
        for (;;) {
            int c = 0;
            if (lane == 0) c = atomicAdd(&tickets[ch], 1);
            c = __shfl_sync(0xffffffffu, c, 0);
            if (c >= CC) break;
            unsigned int h = hs[c];
            int m = (int)(h >> 16);
            if (m == 0) continue;
            int st = (int)(h & 0xffffu);              // 4-aligned
            int n4 = (m + 3) >> 2;
            const uint4* pp = (const uint4*)(pre + st);
            float a0 = 0.0f, a1 = 0.0f, a2 = 0.0f, a3 = 0.0f;
            for (int q = 0; q < n4; q++) {
                uint4 u = pp[q];                       // 4 packed row descriptors
                a0 += tile[(u.x & 0xffffu) + (lane ^ (u.x >> 16))];
                a1 += tile[(u.y & 0xffffu) + (lane ^ (u.y >> 16))];
                a2 += tile[(u.z & 0xffffu) + (lane ^ (u.z >> 16))];
                a3 += tile[(u.w & 0xffffu) + (lane ^ (u.w >> 16))];
            }
            atomicAdd(gS + c * DD, (a0 + a1) + (a2 + a3));
        }
        // next chunk needs a fresh ticket counter — tickets[ch] used once. (per-chunk slots)
    }

    // sumsq reduction: lane -> warp -> block -> global
    #pragma unroll
    for (int o = 16; o > 0; o >>= 1)
        sumsq += __shfl_xor_sync(0xffffffffu, sumsq, o);
    if (lane == 0) wred[wid] = sumsq;
    __syncthreads();
    if (tid == 0) {
        float s = 0.0f;
        #pragma unroll
        for (int w = 0; w < NWARP; w++) s += wred[w];
        atomicAdd(&g_loss, s);
    }

    // ---- Last-block finalize ----
    __threadfence();
    if (tid == 0) tick[0] = atomicAdd(&g_done, 1u);
    __syncthreads();
    if (tick[0] == GRID - 1) {
        __threadfence();
        float part = 0.0f;
        for (int i = tid; i < CC * DD; i += THREADS) {
            float s = 0.0f;
            #pragma unroll
            for (int r = 0; r < NREP; r++) { s += g_S[r][i]; g_S[r][i] = 0.0f; }
            int   c   = i >> 7;
            int   cnt = g_count[c];
            float cen = centers[i];
            out[1 + i] = (cnt > 0) ? (cen - __fdividef(s, (float)cnt)) : 0.0f;
            part += cen * ((float)cnt * cen - 2.0f * s);   // cross terms
        }
        #pragma unroll
        for (int o = 16; o > 0; o >>= 1)
            part += __shfl_xor_sync(0xffffffffu, part, o);
        if (lane == 0) wred[wid] = part;
        __syncthreads();
        if (tid == 0) {
            float t = 0.0f;
            #pragma unroll
            for (int w = 0; w < NWARP; w++) t += wred[w];
            out[0] = (g_loss + t) / 33554432.0f;           // / (N*D)
            g_loss = 0.0f; g_done = 0u;
        }
        if (tid < CC) g_count[tid] = 0;
    }
}

extern "C" void kernel_launch(void* const* d_in, const int* in_sizes, int n_in,
                              void* d_out, int out_size) {
    const float* feature = 0;
    const int*   label   = 0;
    const float* centers = 0;
    for (int i = 0; i < n_in; i++) {
        if (in_sizes[i] == BB * DD * TT)      feature = (const float*)d_in[i];
        else if (in_sizes[i] == BB * TT)      label   = (const int*)d_in[i];
        else if (in_sizes[i] == CC * DD)      centers = (const float*)d_in[i];
    }
    float* out = (float*)d_out;
    (void)out_size;

    cudaFuncSetAttribute(cl_fused_kernel,
                         cudaFuncAttributeMaxDynamicSharedMemorySize, SM_TOTAL);

    cl_fused_kernel<<<GRID, THREADS, SM_TOTAL>>>(feature, label, centers, out);
}

// round 7
// speedup vs baseline: 1.0636x; 1.0636x over previous
#include <cuda_runtime.h>

// Problem constants
#define BB 128
#define DD 128
#define TT 2048
#define CC 64
#define TILE_T 512
#define NTILES 4
#define DCH 32
#define NCH 4
#define THREADS 512
#define NWARP (THREADS / 32)     // 16
#define PITCH 33
#define GRID (BB * NTILES)       // 512
#define NREP 8                   // g_S replicas to spread L2 atomic conflicts
#define ZOFF (TILE_T * PITCH)    // zero-region base index inside tile (16896)
#define PRE_N (TILE_T + CC * 3)  // padded order capacity (704)

// Scratch (allocation-free; self-reset each run so graph replays are identical)
__device__ float        g_S[NREP][CC * DD];
__device__ float        g_loss;
__device__ int          g_count[CC];
__device__ unsigned int g_done;

// Dynamic smem layout (bytes), 16B-aligned fields
#define SM_TILE_OFF   0
#define SM_TILE_BYTES ((TILE_T * PITCH + 32) * 4)          // 67712 (incl. zero region)
#define SM_PRE_OFF    (SM_TILE_OFF + SM_TILE_BYTES)
#define SM_PRE_BYTES  (PRE_N * 4)                          // 2816
#define SM_LABS_OFF   (SM_PRE_OFF + SM_PRE_BYTES)
#define SM_HIST_OFF   (SM_LABS_OFF + TILE_T)
#define SM_HS_OFF     (SM_HIST_OFF + CC * 4)
#define SM_CUR_OFF    (SM_HS_OFF + CC * 4)
#define SM_TICK4_OFF  (SM_CUR_OFF + CC * 4)
#define SM_WRED_OFF   (SM_TICK4_OFF + NCH * 4)
#define SM_WTOT_OFF   (SM_WRED_OFF + NWARP * 4)
#define SM_TICK_OFF   (SM_WTOT_OFF + 8)
#define SM_TOTAL      (SM_TICK_OFF + 16)

__global__ __launch_bounds__(THREADS, 2)
void cl_fused_kernel(const float* __restrict__ feature,
                     const int* __restrict__ label,
                     const float* __restrict__ centers,
                     float* __restrict__ out) {
    extern __shared__ char sm[];
    float*         tile    = (float*)(sm + SM_TILE_OFF);
    unsigned int*  pre     = (unsigned int*)(sm + SM_PRE_OFF);
    unsigned char* labs    = (unsigned char*)(sm + SM_LABS_OFF);
    int*           hist    = (int*)(sm + SM_HIST_OFF);
    unsigned int*  hs      = (unsigned int*)(sm + SM_HS_OFF); // start | (m<<16)
    int*           cursor  = (int*)(sm + SM_CUR_OFF);
    int*           tickets = (int*)(sm + SM_TICK4_OFF);
    float*         wred    = (float*)(sm + SM_WRED_OFF);
    int*           wtot    = (int*)(sm + SM_WTOT_OFF);
    unsigned int*  tick    = (unsigned int*)(sm + SM_TICK_OFF);

    const int tid  = threadIdx.x;
    const int lane = tid & 31;
    const int wid  = tid >> 5;
    const int b    = blockIdx.x >> 2;
    const int t0   = (blockIdx.x & 3) * TILE_T;
    const int rep  = blockIdx.x & (NREP - 1);

    const int t4   = tid & 127;       // float4 slot along t
    const int dd0  = tid >> 7;        // 0..3
    const int sw   = t4 & 31;         // swizzle key
    const int trow = t4 * (4 * PITCH);

    const float4* f4b = (const float4*)feature
        + ((long long)b * DD) * (TT / 4) + (t0 >> 2) + t4;

    // Full-chunk register prefetch (8 float4 = 512B/thread in flight).
    // This is the load-latency hider: issue-to-use distance = one full phase.
    float4 v[8];
    #pragma unroll
    for (int k = 0; k < 8; k++)
        v[k] = f4b[(long long)(dd0 + 4 * k) * (TT / 4)];

    // ---- Prologue: histogram, padded scan, packed-order scatter ----
    if (tid < CC) hist[tid] = 0;
    if (tid < NCH) tickets[tid] = 0;
    if (tid < 32) tile[ZOFF + tid] = 0.0f;            // zero region for padding
    for (int i = tid; i < PRE_N; i += THREADS)
        pre[i] = (unsigned int)ZOFF;                  // sentinel -> reads zeros
    __syncthreads();

    if (tid < TILE_T) {
        int l = label[b * TT + t0 + tid] & (CC - 1);
        labs[tid] = (unsigned char)l;
        atomicAdd(&hist[l], 1);
    }
    __syncthreads();

    {   // exclusive scan of 4-padded class sizes (warps 0/1 + carry)
        int m  = (tid < CC) ? hist[tid] : 0;
        int p4 = (m + 3) & ~3;
        int incl = p4;
        #pragma unroll
        for (int o = 1; o < 32; o <<= 1) {
            int n = __shfl_up_sync(0xffffffffu, incl, o);
            if (lane >= o) incl += n;
        }
        if (wid < 2 && lane == 31) wtot[wid] = incl;
        __syncthreads();
        if (tid < CC) {
            int st = incl - p4 + (wid == 1 ? wtot[0] : 0);
            hs[tid]     = (unsigned int)st | ((unsigned int)m << 16);
            cursor[tid] = st;
        }
        __syncthreads();
    }

    if (tid < TILE_T) {
        int pos = atomicAdd(&cursor[labs[tid]], 1);
        // packed row descriptor: low16 = t*PITCH, high = swizzle key (t>>2)&31
        pre[pos] = (unsigned int)(tid * PITCH) | (((unsigned int)(tid >> 2) & 31u) << 16);
    }
    if (tid < CC) atomicAdd(&g_count[tid], hist[tid]);

    float sumsq = 0.0f;

    // ---- Main loop over 4 d-chunks ----
    for (int ch = 0; ch < NCH; ch++) {
        __syncthreads();   // tile free (previous gather done)

        // Store full chunk from regs to XOR-swizzled tile + sum-of-squares.
        #pragma unroll
        for (int k = 0; k < 8; k++) {
            int base = trow + ((dd0 + 4 * k) ^ sw);
            tile[base]             = v[k].x;
            tile[base + PITCH]     = v[k].y;
            tile[base + 2 * PITCH] = v[k].z;
            tile[base + 3 * PITCH] = v[k].w;
            sumsq = fmaf(v[k].x, v[k].x, sumsq);
            sumsq = fmaf(v[k].y, v[k].y, sumsq);
            sumsq = fmaf(v[k].z, v[k].z, sumsq);
            sumsq = fmaf(v[k].w, v[k].w, sumsq);
        }
        __syncthreads();   // tile ready

        // Prefetch NEXT chunk now; its latency hides behind the whole gather.
        if (ch < NCH - 1) {
            const float4* f4n = f4b + (long long)((ch + 1) * DCH) * (TT / 4);
            #pragma unroll
            for (int k = 0; k < 8; k++)
                v[k] = f4n[(long long)(dd0 + 4 * k) * (TT / 4)];
        }

        // Work-stealing gather: warps grab classes off a per-chunk ticket.
        float* gS = &g_S[rep][ch * DCH + lane];
        for (;;) {
            int c = 0;
            if (lane == 0) c = atomicAdd(&tickets[ch], 1);
            c = __shfl_sync(0xffffffffu, c, 0);
            if (c >= CC) break;
            unsigned int h = hs[c];
            int m = (int)(h >> 16);
            if (m == 0) continue;
            int st = (int)(h & 0xffffu);              // 4-aligned
            int n4 = (m + 3) >> 2;
            const uint4* pp = (const uint4*)(pre + st);
            float a0 = 0.0f, a1 = 0.0f, a2 = 0.0f, a3 = 0.0f;
            for (int q = 0; q < n4; q++) {
                uint4 u = pp[q];                       // 4 packed row descriptors
                a0 += tile[(u.x & 0xffffu) + (lane ^ (u.x >> 16))];
                a1 += tile[(u.y & 0xffffu) + (lane ^ (u.y >> 16))];
                a2 += tile[(u.z & 0xffffu) + (lane ^ (u.z >> 16))];
                a3 += tile[(u.w & 0xffffu) + (lane ^ (u.w >> 16))];
            }
            atomicAdd(gS + c * DD, (a0 + a1) + (a2 + a3));
        }
    }

    // sumsq reduction: lane -> warp -> block -> global
    #pragma unroll
    for (int o = 16; o > 0; o >>= 1)
        sumsq += __shfl_xor_sync(0xffffffffu, sumsq, o);
    if (lane == 0) wred[wid] = sumsq;
    __syncthreads();
    if (tid == 0) {
        float s = 0.0f;
        #pragma unroll
        for (int w = 0; w < NWARP; w++) s += wred[w];
        atomicAdd(&g_loss, s);
    }

    // ---- Last-block finalize ----
    __threadfence();
    if (tid == 0) tick[0] = atomicAdd(&g_done, 1u);
    __syncthreads();
    if (tick[0] == GRID - 1) {
        __threadfence();
        float part = 0.0f;
        for (int i = tid; i < CC * DD; i += THREADS) {
            float s = 0.0f;
            #pragma unroll
            for (int r = 0; r < NREP; r++) { s += g_S[r][i]; g_S[r][i] = 0.0f; }
            int   c   = i >> 7;
            int   cnt = g_count[c];
            float cen = centers[i];
            out[1 + i] = (cnt > 0) ? (cen - __fdividef(s, (float)cnt)) : 0.0f;
            part += cen * ((float)cnt * cen - 2.0f * s);   // loss cross terms
        }
        #pragma unroll
        for (int o = 16; o > 0; o >>= 1)
            part += __shfl_xor_sync(0xffffffffu, part, o);
        if (lane == 0) wred[wid] = part;
        __syncthreads();
        if (tid == 0) {
            float t = 0.0f;
            #pragma unroll
            for (int w = 0; w < NWARP; w++) t += wred[w];
            out[0] = (g_loss + t) / 33554432.0f;           // / (N*D)
            g_loss = 0.0f; g_done = 0u;
        }
        if (tid < CC) g_count[tid] = 0;
    }
}

extern "C" void kernel_launch(void* const* d_in, const int* in_sizes, int n_in,
                              void* d_out, int out_size) {
    const float* feature = 0;
    const int*   label   = 0;
    const float* centers = 0;
    for (int i = 0; i < n_in; i++) {
        if (in_sizes[i] == BB * DD * TT)      feature = (const float*)d_in[i];
        else if (in_sizes[i] == BB * TT)      label   = (const int*)d_in[i];
        else if (in_sizes[i] == CC * DD)      centers = (const float*)d_in[i];
    }
    float* out = (float*)d_out;
    (void)out_size;

    cudaFuncSetAttribute(cl_fused_kernel,
                         cudaFuncAttributeMaxDynamicSharedMemorySize, SM_TOTAL);

    cl_fused_kernel<<<GRID, THREADS, SM_TOTAL>>>(feature, label, centers, out);
}

// round 8
// speedup vs baseline: 1.1507x; 1.0819x over previous
#include <cuda_runtime.h>

// Problem constants
#define BB 128
#define DD 128
#define TT 2048
#define CC 64
#define TILE_T 512
#define NTILES 4
#define DCH 32
#define NCH 4
#define THREADS 512
#define NWARP (THREADS / 32)     // 16
#define PITCH 33
#define GRID (BB * NTILES)       // 512
#define NREP 8
#define ZOFF (TILE_T * PITCH)    // zero-region base index inside tile (16896)
#define PRE_N (TILE_T + CC * 3)  // padded descriptor capacity (704)

// Scratch (allocation-free; self-reset each run so graph replays are identical)
__device__ float        g_S[NREP][CC * DD];
__device__ float        g_loss;
__device__ int          g_count[CC];
__device__ unsigned int g_done;

// Dynamic smem layout (bytes), 16B-aligned fields
#define SM_TILE_OFF   0
#define SM_TILE_BYTES ((TILE_T * PITCH + 32) * 4)          // 67712 incl zero region
#define SM_PRE_OFF    (SM_TILE_OFF + SM_TILE_BYTES)        // 16B aligned
#define SM_PRE_BYTES  (PRE_N * 4)
#define SM_HIST_OFF   (SM_PRE_OFF + SM_PRE_BYTES)
#define SM_START_OFF  (SM_HIST_OFF + CC * 4)
#define SM_CUR_OFF    (SM_START_OFF + CC * 4)
#define SM_WRED_OFF   (SM_CUR_OFF + CC * 4)
#define SM_WTOT_OFF   (SM_WRED_OFF + NWARP * 4)
#define SM_PTOT_OFF   (SM_WTOT_OFF + 8)
#define SM_TICK_OFF   (SM_PTOT_OFF + 4)
#define SM_TOTAL      (SM_TICK_OFF + 16)

// Gather step: descriptor x = base(t*33)[0:16) | key[16:21) | class[21:27)
#define GPROC(x) {                                                        \
    int c_ = (int)((x) >> 21);                                            \
    if (c_ != cur) {                                                      \
        if (cur >= 0) atomicAdd(gS + cur * DD, acc);                      \
        cur = c_; acc = 0.0f;                                             \
    }                                                                     \
    acc += tile[((x) & 0xFFFFu) + (lane ^ (((x) >> 16) & 31u))];          \
}

__global__ __launch_bounds__(THREADS, 2)
void cl_fused_kernel(const float* __restrict__ feature,
                     const int* __restrict__ label,
                     const float* __restrict__ centers,
                     float* __restrict__ out) {
    extern __shared__ char sm[];
    float*         tile    = (float*)(sm + SM_TILE_OFF);
    unsigned int*  pre     = (unsigned int*)(sm + SM_PRE_OFF);
    int*           hist    = (int*)(sm + SM_HIST_OFF);
    int*           starts  = (int*)(sm + SM_START_OFF);
    int*           cursor  = (int*)(sm + SM_CUR_OFF);
    float*         wred    = (float*)(sm + SM_WRED_OFF);
    int*           wtot    = (int*)(sm + SM_WTOT_OFF);
    int*           sptot   = (int*)(sm + SM_PTOT_OFF);
    unsigned int*  tick    = (unsigned int*)(sm + SM_TICK_OFF);

    const int tid  = threadIdx.x;
    const int lane = tid & 31;
    const int wid  = tid >> 5;
    const int b    = blockIdx.x >> 2;
    const int t0   = (blockIdx.x & 3) * TILE_T;
    const int rep  = blockIdx.x & (NREP - 1);

    const int t4   = tid & 127;       // float4 slot along t (load geometry)
    const int dd0  = tid >> 7;        // 0..3
    const int sw   = t4 & 31;         // store swizzle key
    const int trow = t4 * (4 * PITCH);

    // Label first (needed soonest), then the full-chunk feature prefetch.
    const int myl = label[b * TT + t0 + tid] & (CC - 1);   // THREADS == TILE_T

    const float4* f4b = (const float4*)feature
        + ((long long)b * DD) * (TT / 4) + (t0 >> 2) + t4;
    float4 v[8];
    #pragma unroll
    for (int k = 0; k < 8; k++)
        v[k] = f4b[(long long)(dd0 + 4 * k) * (TT / 4)];

    // ---- Prologue: histogram, padded scan, descriptor scatter ----
    if (tid < CC) hist[tid] = 0;
    if (tid < 32) tile[ZOFF + tid] = 0.0f;                 // zero region
    __syncthreads();

    atomicAdd(&hist[myl], 1);
    __syncthreads();

    {   // exclusive scan of 4-padded class sizes (warps 0/1 + carry)
        int m  = (tid < CC) ? hist[tid] : 0;
        int p4 = (m + 3) & ~3;
        int incl = p4;
        #pragma unroll
        for (int o = 1; o < 32; o <<= 1) {
            int n = __shfl_up_sync(0xffffffffu, incl, o);
            if (lane >= o) incl += n;
        }
        if (wid < 2 && lane == 31) wtot[wid] = incl;
        __syncthreads();
        if (tid < CC) {
            int st = incl - p4 + (wid == 1 ? wtot[0] : 0);
            starts[tid] = st;
            cursor[tid] = st;
        }
        if (tid == 0) sptot[0] = wtot[0] + wtot[1];
        __syncthreads();
    }

    {   // scatter row descriptors; then per-class padding -> zero region
        int pos = atomicAdd(&cursor[myl], 1);
        pre[pos] = (unsigned int)(tid * PITCH)
                 | (((unsigned int)(tid >> 2) & 31u) << 16)
                 | ((unsigned int)myl << 21);
        if (tid < CC) {
            int m  = hist[tid];
            int st = starts[tid];
            int p4 = (m + 3) & ~3;
            for (int k = m; k < p4; k++)
                pre[st + k] = (unsigned int)ZOFF | ((unsigned int)tid << 21);
            atomicAdd(&g_count[tid], m);
        }
    }

    float sumsq = 0.0f;

    // ---- Main loop over 4 d-chunks ----
    for (int ch = 0; ch < NCH; ch++) {
        __syncthreads();   // tile free (previous gather done)

        // Store full chunk from regs into XOR-swizzled tile + sum of squares.
        #pragma unroll
        for (int k = 0; k < 8; k++) {
            int base = trow + ((dd0 + 4 * k) ^ sw);
            tile[base]             = v[k].x;
            tile[base + PITCH]     = v[k].y;
            tile[base + 2 * PITCH] = v[k].z;
            tile[base + 3 * PITCH] = v[k].w;
            sumsq = fmaf(v[k].x, v[k].x, sumsq);
            sumsq = fmaf(v[k].y, v[k].y, sumsq);
            sumsq = fmaf(v[k].z, v[k].z, sumsq);
            sumsq = fmaf(v[k].w, v[k].w, sumsq);
        }

        // Prefetch NEXT chunk BEFORE the barrier: issue-to-use distance =
        // barrier wait + entire gather phase.
        if (ch < NCH - 1) {
            const float4* f4n = f4b + (long long)((ch + 1) * DCH) * (TT / 4);
            #pragma unroll
            for (int k = 0; k < 8; k++)
                v[k] = f4n[(long long)(dd0 + 4 * k) * (TT / 4)];
        }
        __syncthreads();   // tile ready

        // Flattened gather: equal contiguous ranges of 4-row groups per warp,
        // class carried in descriptor, accumulator flushed on class change.
        {
            const int groups = sptot[0] >> 2;
            const int qs = (wid * groups) >> 4;        // wid*groups/NWARP
            const int qe = ((wid + 1) * groups) >> 4;
            const uint4* pre4 = (const uint4*)pre;
            float* gS = &g_S[rep][ch * DCH + lane];
            int   cur = -1;
            float acc = 0.0f;
            for (int q = qs; q < qe; q++) {
                uint4 u = pre4[q];
                GPROC(u.x); GPROC(u.y); GPROC(u.z); GPROC(u.w);
            }
            if (cur >= 0) atomicAdd(gS + cur * DD, acc);
        }
    }

    // sumsq reduction: lane -> warp -> block -> global
    #pragma unroll
    for (int o = 16; o > 0; o >>= 1)
        sumsq += __shfl_xor_sync(0xffffffffu, sumsq, o);
    if (lane == 0) wred[wid] = sumsq;
    __syncthreads();
    if (tid == 0) {
        float s = 0.0f;
        #pragma unroll
        for (int w = 0; w < NWARP; w++) s += wred[w];
        atomicAdd(&g_loss, s);
    }

    // ---- Last-block finalize ----
    __threadfence();
    if (tid == 0) tick[0] = atomicAdd(&g_done, 1u);
    __syncthreads();
    if (tick[0] == GRID - 1) {
        __threadfence();
        float part = 0.0f;
        for (int i = tid; i < CC * DD; i += THREADS) {
            float s = 0.0f;
            #pragma unroll
            for (int r = 0; r < NREP; r++) { s += g_S[r][i]; g_S[r][i] = 0.0f; }
            int   c   = i >> 7;
            int   cnt = g_count[c];
            float cen = centers[i];
            out[1 + i] = (cnt > 0) ? (cen - __fdividef(s, (float)cnt)) : 0.0f;
            part += cen * ((float)cnt * cen - 2.0f * s);   // loss cross terms
        }
        #pragma unroll
        for (int o = 16; o > 0; o >>= 1)
            part += __shfl_xor_sync(0xffffffffu, part, o);
        if (lane == 0) wred[wid] = part;
        __syncthreads();
        if (tid == 0) {
            float t = 0.0f;
            #pragma unroll
            for (int w = 0; w < NWARP; w++) t += wred[w];
            out[0] = (g_loss + t) / 33554432.0f;           // / (N*D)
            g_loss = 0.0f; g_done = 0u;
        }
        if (tid < CC) g_count[tid] = 0;
    }
}

extern "C" void kernel_launch(void* const* d_in, const int* in_sizes, int n_in,
                              void* d_out, int out_size) {
    const float* feature = 0;
    const int*   label   = 0;
    const float* centers = 0;
    for (int i = 0; i < n_in; i++) {
        if (in_sizes[i] == BB * DD * TT)      feature = (const float*)d_in[i];
        else if (in_sizes[i] == BB * TT)      label   = (const int*)d_in[i];
        else if (in_sizes[i] == CC * DD)      centers = (const float*)d_in[i];
    }
    float* out = (float*)d_out;
    (void)out_size;

    cudaFuncSetAttribute(cl_fused_kernel,
                         cudaFuncAttributeMaxDynamicSharedMemorySize, SM_TOTAL);

    cl_fused_kernel<<<GRID, THREADS, SM_TOTAL>>>(feature, label, centers, out);
}

// round 9
// speedup vs baseline: 1.2198x; 1.0601x over previous
#include <cuda_runtime.h>

// Problem constants
#define BB 128
#define DD 128
#define TT 2048
#define CC 64
#define TILE_T 512
#define DCH 32
#define NCH 4
#define THREADS 512
#define NWARP (THREADS / 32)     // 16
#define PITCH 33
#define NTILE 512                // total work tiles
#define GRID 304                 // persistent: 152 SMs x 2 CTAs
#define NREP 8

// Scratch (allocation-free; self-reset each run so graph replays are identical)
__device__ float        g_S[NREP][CC * DD];
__device__ float        g_loss;
__device__ int          g_count[CC];
__device__ unsigned int g_done;
__device__ unsigned int g_ticket;

// Dynamic smem layout (bytes)
#define SM_TILE_OFF   0
#define SM_TILE_BYTES (TILE_T * PITCH * 4)                 // 67584
#define SM_ORDER_OFF  (SM_TILE_OFF + SM_TILE_BYTES)
#define SM_HIST_OFF   (SM_ORDER_OFF + TILE_T * 2)
#define SM_START_OFF  (SM_HIST_OFF + CC * 4)
#define SM_CUR_OFF    (SM_START_OFF + CC * 4)
#define SM_WRED_OFF   (SM_CUR_OFF + CC * 4)
#define SM_WTOT_OFF   (SM_WRED_OFF + NWARP * 4)
#define SM_SLOT_OFF   (SM_WTOT_OFF + 8)                    // [0]=cur,[1]=next ticket
#define SM_TICK_OFF   (SM_SLOT_OFF + 8)
#define SM_TOTAL      (SM_TICK_OFF + 8)

__global__ __launch_bounds__(THREADS, 2)
void cl_fused_kernel(const float* __restrict__ feature,
                     const int* __restrict__ label,
                     const float* __restrict__ centers,
                     float* __restrict__ out) {
    extern __shared__ char sm[];
    float*          tile   = (float*)(sm + SM_TILE_OFF);
    unsigned short* order  = (unsigned short*)(sm + SM_ORDER_OFF);
    int*            hist   = (int*)(sm + SM_HIST_OFF);
    int*            starts = (int*)(sm + SM_START_OFF);
    int*            cursor = (int*)(sm + SM_CUR_OFF);
    float*          wred   = (float*)(sm + SM_WRED_OFF);
    int*            wtot   = (int*)(sm + SM_WTOT_OFF);
    unsigned int*   slot   = (unsigned int*)(sm + SM_SLOT_OFF);
    unsigned int*   tick   = (unsigned int*)(sm + SM_TICK_OFF);

    const int tid  = threadIdx.x;
    const int lane = tid & 31;
    const int wid  = tid >> 5;

    const int t4   = tid & 127;       // float4 slot along t (load geometry)
    const int dd0  = tid >> 7;        // 0..3
    const int sw   = t4 & 31;         // store swizzle key
    const int trow = t4 * (4 * PITCH);

    // First ticket
    if (tid == 0) slot[0] = atomicAdd(&g_ticket, 1u);
    __syncthreads();
    unsigned int cur = slot[0];

    // Prefetch for first tile (full chunk 0 + label), if we got work.
    int myl = 0;
    const float4* f4b = (const float4*)feature;
    float4 v[8];
    if (cur < NTILE) {
        const int b  = (int)(cur >> 2);
        const int t0 = ((int)cur & 3) * TILE_T;
        myl = label[b * TT + t0 + tid] & (CC - 1);
        f4b = (const float4*)feature + ((long long)b * DD) * (TT / 4) + (t0 >> 2) + t4;
        #pragma unroll
        for (int k = 0; k < 8; k++)
            v[k] = f4b[(long long)(dd0 + 4 * k) * (TT / 4)];
    }

    float sumsq = 0.0f;

    while (cur < NTILE) {
        const int rep = (int)cur & (NREP - 1);

        // ---- Prologue: histogram, padded-free scan, counting-sort scatter ----
        __syncthreads();                    // previous tile's gather fully done
        if (tid < CC) hist[tid] = 0;
        __syncthreads();
        atomicAdd(&hist[myl], 1);
        __syncthreads();

        {   // exclusive scan over 64 class sizes (warps 0/1 + carry)
            int m = (tid < CC) ? hist[tid] : 0;
            int incl = m;
            #pragma unroll
            for (int o = 1; o < 32; o <<= 1) {
                int n = __shfl_up_sync(0xffffffffu, incl, o);
                if (lane >= o) incl += n;
            }
            if (wid < 2 && lane == 31) wtot[wid] = incl;
            __syncthreads();
            if (tid < CC) {
                int st = incl - m + (wid == 1 ? wtot[0] : 0);
                starts[tid] = st;
                cursor[tid] = st;
            }
            __syncthreads();
        }

        {   // scatter tile-local row index grouped by class
            int pos = atomicAdd(&cursor[myl], 1);
            order[pos] = (unsigned short)tid;
        }
        if (tid < CC) atomicAdd(&g_count[tid], hist[tid]);

        unsigned int nxt = NTILE;

        // ---- 4 d-chunks ----
        for (int ch = 0; ch < NCH; ch++) {
            __syncthreads();   // tile free (previous gather done)

            // Store full chunk from regs into XOR-swizzled tile + sum of squares.
            #pragma unroll
            for (int k = 0; k < 8; k++) {
                int base = trow + ((dd0 + 4 * k) ^ sw);
                tile[base]             = v[k].x;
                tile[base + PITCH]     = v[k].y;
                tile[base + 2 * PITCH] = v[k].z;
                tile[base + 3 * PITCH] = v[k].w;
                sumsq = fmaf(v[k].x, v[k].x, sumsq);
                sumsq = fmaf(v[k].y, v[k].y, sumsq);
                sumsq = fmaf(v[k].z, v[k].z, sumsq);
                sumsq = fmaf(v[k].w, v[k].w, sumsq);
            }

            // Prefetch BEFORE the barrier: issue-to-use distance = barrier wait
            // + entire gather phase (+ prologue, for the cross-tile case).
            if (ch < NCH - 1) {
                const float4* f4n = f4b + (long long)((ch + 1) * DCH) * (TT / 4);
                #pragma unroll
                for (int k = 0; k < 8; k++)
                    v[k] = f4n[(long long)(dd0 + 4 * k) * (TT / 4)];
                // Grab the NEXT tile's ticket during chunk 2; visible to all
                // threads after chunk 3's "tile free" barrier.
                if (ch == 2 && tid == 0) slot[1] = atomicAdd(&g_ticket, 1u);
            } else {
                nxt = slot[1];             // ordered by this chunk's earlier barrier
                if (nxt < NTILE) {         // prefetch next tile's chunk 0 + label
                    const int nb  = (int)(nxt >> 2);
                    const int nt0 = ((int)nxt & 3) * TILE_T;
                    myl = label[nb * TT + nt0 + tid] & (CC - 1);
                    f4b = (const float4*)feature
                        + ((long long)nb * DD) * (TT / 4) + (nt0 >> 2) + t4;
                    #pragma unroll
                    for (int k = 0; k < 8; k++)
                        v[k] = f4b[(long long)(dd0 + 4 * k) * (TT / 4)];
                }
            }
            __syncthreads();   // tile ready

            // Per-class gather (R5-proven). Warp w owns classes w, w+16, ...
            float* gS = &g_S[rep][ch * DCH + lane];
            for (int c = wid; c < CC; c += NWARP) {
                const int m  = hist[c];
                const int st = starts[c];
                float s0 = 0.0f, s1 = 0.0f;
                int j = 0;
                for (; j + 1 < m; j += 2) {
                    int ta = order[st + j];
                    int tb = order[st + j + 1];
                    s0 += tile[ta * PITCH + (lane ^ ((ta >> 2) & 31))];
                    s1 += tile[tb * PITCH + (lane ^ ((tb >> 2) & 31))];
                }
                if (j < m) {
                    int ta = order[st + j];
                    s0 += tile[ta * PITCH + (lane ^ ((ta >> 2) & 31))];
                }
                atomicAdd(gS + c * DD, s0 + s1);
            }
        }

        cur = nxt;
    }

    // sumsq reduction: lane -> warp -> block -> global (once per block)
    #pragma unroll
    for (int o = 16; o > 0; o >>= 1)
        sumsq += __shfl_xor_sync(0xffffffffu, sumsq, o);
    if (lane == 0) wred[wid] = sumsq;
    __syncthreads();
    if (tid == 0) {
        float s = 0.0f;
        #pragma unroll
        for (int w = 0; w < NWARP; w++) s += wred[w];
        atomicAdd(&g_loss, s);
    }

    // ---- Last-block finalize ----
    __threadfence();
    if (tid == 0) tick[0] = atomicAdd(&g_done, 1u);
    __syncthreads();
    if (tick[0] == GRID - 1) {
        __threadfence();
        float part = 0.0f;
        for (int i = tid; i < CC * DD; i += THREADS) {
            float s = 0.0f;
            #pragma unroll
            for (int r = 0; r < NREP; r++) { s += g_S[r][i]; g_S[r][i] = 0.0f; }
            int   c   = i >> 7;
            int   cnt = g_count[c];
            float cen = centers[i];
            out[1 + i] = (cnt > 0) ? (cen - __fdividef(s, (float)cnt)) : 0.0f;
            part += cen * ((float)cnt * cen - 2.0f * s);   // loss cross terms
        }
        #pragma unroll
        for (int o = 16; o > 0; o >>= 1)
            part += __shfl_xor_sync(0xffffffffu, part, o);
        if (lane == 0) wred[wid] = part;
        __syncthreads();
        if (tid == 0) {
            float t = 0.0f;
            #pragma unroll
            for (int w = 0; w < NWARP; w++) t += wred[w];
            out[0] = (g_loss + t) / 33554432.0f;           // / (N*D)
            g_loss = 0.0f; g_done = 0u; g_ticket = 0u;
        }
        if (tid < CC) g_count[tid] = 0;
    }
}

extern "C" void kernel_launch(void* const* d_in, const int* in_sizes, int n_in,
                              void* d_out, int out_size) {
    const float* feature = 0;
    const int*   label   = 0;
    const float* centers = 0;
    for (int i = 0; i < n_in; i++) {
        if (in_sizes[i] == BB * DD * TT)      feature = (const float*)d_in[i];
        else if (in_sizes[i] == BB * TT)      label   = (const int*)d_in[i];
        else if (in_sizes[i] == CC * DD)      centers = (const float*)d_in[i];
    }
    float* out = (float*)d_out;
    (void)out_size;

    cudaFuncSetAttribute(cl_fused_kernel,
                         cudaFuncAttributeMaxDynamicSharedMemorySize, SM_TOTAL);

    cl_fused_kernel<<<GRID, THREADS, SM_TOTAL>>>(feature, label, centers, out);
}